// round 6
// baseline (speedup 1.0000x reference)
#include <cuda_runtime.h>
#include <math.h>

#define G      1024
#define GI     (G - 2)
#define B      4
#define N_TOT  (B * G * G)

__device__ float g_w  [N_TOT];   // exp(mu * prev_pre)
__device__ float g_h  [N_TOT];   // 0.5 / y3   (0 on boundary)
__device__ float g_F  [N_TOT];   // f*H^2 / y3 (0 on boundary)
__device__ float g_u0 [N_TOT];
__device__ float g_u1 [N_TOT];

// ---------- fused precompute: w, h, F in one pass ----------
__global__ void k_pre(const float* __restrict__ prev, const float* __restrict__ f,
                      const float* __restrict__ mu) {
    int j0 = (blockIdx.x * blockDim.x + threadIdx.x) * 4;   // 0..1020
    int i  = blockIdx.y;
    int b  = blockIdx.z;
    int base = (b * G + i) * G + j0;
    float m = mu[0];

    float4 pC = *(const float4*)(prev + base);
    float4 pN = (i > 0)     ? *(const float4*)(prev + base - G) : make_float4(0, 0, 0, 0);
    float4 pS = (i < G - 1) ? *(const float4*)(prev + base + G) : make_float4(0, 0, 0, 0);
    float  pL = (j0 > 0)     ? prev[base - 1] : 0.0f;
    float  pR = (j0 < G - 4) ? prev[base + 4] : 0.0f;

    float wc[6] = { expf(m * pL), expf(m * pC.x), expf(m * pC.y),
                    expf(m * pC.z), expf(m * pC.w), expf(m * pR) };
    float wn[4] = { expf(m * pN.x), expf(m * pN.y), expf(m * pN.z), expf(m * pN.w) };
    float ws[4] = { expf(m * pS.x), expf(m * pS.y), expf(m * pS.z), expf(m * pS.w) };

    *(float4*)(g_w + base) = make_float4(wc[1], wc[2], wc[3], wc[4]);

    float4 fC = *(const float4*)(f + base);
    float ff[4] = { fC.x, fC.y, fC.z, fC.w };

    float h[4], Fo[4];
    bool rowIn = (i >= 1 && i <= G - 2);
    const float HH = (1.0f / 1023.0f) * (1.0f / 1023.0f);
#pragma unroll
    for (int k = 0; k < 4; ++k) {
        int j = j0 + k;
        bool in = rowIn && (j >= 1 && j <= G - 2);
        float y3  = 0.5f * (wn[k] + ws[k] + wc[k] + wc[k + 2]) + 2.0f * wc[k + 1];
        float iy3 = 1.0f / y3;
        h[k]  = in ? 0.5f * iy3       : 0.0f;
        Fo[k] = in ? ff[k] * HH * iy3 : 0.0f;
    }
    *(float4*)(g_h + base) = make_float4(h[0], h[1], h[2], h[3]);
    *(float4*)(g_F + base) = make_float4(Fo[0], Fo[1], Fo[2], Fo[3]);
}

// ---------- init u0 (interior = pre, border = 0), zero u1 border ----------
__global__ void k_init(const float* __restrict__ pre) {
    int j = blockIdx.x * blockDim.x + threadIdx.x;
    int i = blockIdx.y;
    int b = blockIdx.z;
    if (j >= G) return;
    int idx = (b * G + i) * G + j;
    bool border = (i == 0 || i == G - 1 || j == 0 || j == G - 1);
    g_u0[idx] = border ? 0.0f : pre[(b * GI + (i - 1)) * GI + (j - 1)];
    if (border) g_u1[idx] = 0.0f;
}

// ---------- 4-wide stencil for one row ----------
__device__ __forceinline__ float4 row_stencil(
    float4 uC, float uL, float uR, float4 uN, float4 uS,
    float4 wCv, float wL, float wR, float4 wNv, float4 wSv,
    float4 h4, float4 F4)
{
    float uc[6] = { uL, uC.x, uC.y, uC.z, uC.w, uR };
    float wc[6] = { wL, wCv.x, wCv.y, wCv.z, wCv.w, wR };
    float un[4] = { uN.x, uN.y, uN.z, uN.w };
    float us[4] = { uS.x, uS.y, uS.z, uS.w };
    float wn[4] = { wNv.x, wNv.y, wNv.z, wNv.w };
    float ws[4] = { wSv.x, wSv.y, wSv.z, wSv.w };
    float hh[4] = { h4.x, h4.y, h4.z, h4.w };
    float ff[4] = { F4.x, F4.y, F4.z, F4.w };
    float r[4];
#pragma unroll
    for (int k = 0; k < 4; ++k) {
        float uW = uc[k], uE = uc[k + 2];
        float s = wc[k + 1] * (uW + uE + un[k] + us[k]);
        s = fmaf(wc[k],     uW,    s);
        s = fmaf(wc[k + 2], uE,    s);
        s = fmaf(wn[k],     un[k], s);
        s = fmaf(ws[k],     us[k], s);
        r[k] = fmaf(hh[k], s, ff[k]);
    }
    return make_float4(r[0], r[1], r[2], r[3]);
}

// ---------- one Jacobi sweep, 2 rows x 4 cols per thread ----------
// i in {1,3,...,1021}: rows i-1..i+2 always in-bounds -> no load guards.
// h=F=0 on boundary makes edge results exactly 0 -> full float4 stores are safe.
template <bool FINAL>
__global__ void __launch_bounds__(256)
k_step(int parity, float* __restrict__ out) {
    int j0 = (blockIdx.x * 32 + threadIdx.x) * 4;          // 0..1020
    int pr = blockIdx.y * 8 + threadIdx.y;                 // row-pair index
    int i  = pr * 2 + 1;                                   // 1,3,...,
    int b  = blockIdx.z;
    if (i > G - 2) return;                                 // i <= 1021
    int idx = (b * G + i) * G + j0;

    const float* __restrict__ u = parity ? g_u1 : g_u0;

    // u rows i-1 .. i+2
    float4 u_m = *(const float4*)(u + idx - G);
    float4 u_0 = *(const float4*)(u + idx);
    float4 u_1 = *(const float4*)(u + idx + G);
    float4 u_2 = *(const float4*)(u + idx + 2 * G);
    // w rows i-1 .. i+2
    float4 w_m = *(const float4*)(g_w + idx - G);
    float4 w_0 = *(const float4*)(g_w + idx);
    float4 w_1 = *(const float4*)(g_w + idx + G);
    float4 w_2 = *(const float4*)(g_w + idx + 2 * G);
    // scalar edge cols for rows i, i+1 (garbage at strip ends only feeds boundary cells where h=F=0)
    float uL0 = u[idx - 1],     uR0 = u[idx + 4];
    float uL1 = u[idx + G - 1], uR1 = u[idx + G + 4];
    float wL0 = g_w[idx - 1],     wR0 = g_w[idx + 4];
    float wL1 = g_w[idx + G - 1], wR1 = g_w[idx + G + 4];

    float4 h0 = *(const float4*)(g_h + idx);
    float4 F0 = *(const float4*)(g_F + idx);
    float4 h1 = *(const float4*)(g_h + idx + G);
    float4 F1 = *(const float4*)(g_F + idx + G);

    float4 r0 = row_stencil(u_0, uL0, uR0, u_m, u_1, w_0, wL0, wR0, w_m, w_1, h0, F0);
    float4 r1 = row_stencil(u_1, uL1, uR1, u_0, u_2, w_1, wL1, wR1, w_0, w_2, h1, F1);

    if (FINAL) {
        long ob0 = ((long)b * GI + (i - 1)) * GI;
        float rr0[4] = { r0.x, r0.y, r0.z, r0.w };
        float rr1[4] = { r1.x, r1.y, r1.z, r1.w };
#pragma unroll
        for (int k = 0; k < 4; ++k) {
            int j = j0 + k;
            if (j >= 1 && j <= G - 2) {
                out[ob0 + (j - 1)] = rr0[k];
                out[ob0 + GI + (j - 1)] = rr1[k];
            }
        }
    } else {
        float* __restrict__ dst = parity ? g_u0 : g_u1;
        *(float4*)(dst + idx)     = r0;
        *(float4*)(dst + idx + G) = r1;
    }
}

extern "C" void kernel_launch(void* const* d_in, const int* in_sizes, int n_in,
                              void* d_out, int out_size) {
    const float* pre  = (const float*)d_in[0];   // [B,1,1022,1022]
    const float* f    = (const float*)d_in[1];   // [B,1,1024,1024]
    const float* mu   = (const float*)d_in[2];   // [1]
    const float* prev = (const float*)d_in[3];   // [B,1,1024,1024]
    // d_in[4] = maxiter (fixed = 20 -> 21 total steps)
    float* out = (float*)d_out;

    // precompute
    dim3 pblk(128, 1, 1);                 // 128 threads x 4 cols = 512 cols
    dim3 pgrd(G / 512, G, B);
    k_pre<<<pgrd, pblk>>>(prev, f, mu);

    dim3 iblk(256, 1, 1);
    dim3 igrd((G + 255) / 256, G, B);
    k_init<<<igrd, iblk>>>(pre);

    // 21 Jacobi sweeps; 2 rows/thread. 511 row-pairs -> 64 y-blocks of 8.
    dim3 sblk(32, 8, 1);
    dim3 sgrd(G / 128, 64, B);            // 8 x 64 x 4 = 2048 blocks, 256 thr
    for (int t = 0; t < 20; ++t) {
        k_step<false><<<sgrd, sblk>>>(t & 1, nullptr);
    }
    k_step<true><<<sgrd, sblk>>>(20 & 1, out);
}

// round 7
// speedup vs baseline: 1.3775x; 1.3775x over previous
#include <cuda_runtime.h>
#include <math.h>

#define G      1024
#define GI     (G - 2)
#define B      4
#define N_TOT  (B * G * G)

__device__ float g_w  [N_TOT];   // exp(mu * prev_pre)
__device__ float g_h  [N_TOT];   // 0.5 / y3   (0 on boundary)
__device__ float g_F  [N_TOT];   // f*H^2 / y3 (0 on boundary)
__device__ float g_u0 [N_TOT];
__device__ float g_u1 [N_TOT];

// ---------- fused precompute: w, h, F in one pass ----------
__global__ void k_pre(const float* __restrict__ prev, const float* __restrict__ f,
                      const float* __restrict__ mu) {
    int j0 = (blockIdx.x * blockDim.x + threadIdx.x) * 4;   // 0..1020
    int i  = blockIdx.y;
    int b  = blockIdx.z;
    int base = (b * G + i) * G + j0;
    float m = mu[0];

    float4 pC = *(const float4*)(prev + base);
    float4 pN = (i > 0)     ? *(const float4*)(prev + base - G) : make_float4(0, 0, 0, 0);
    float4 pS = (i < G - 1) ? *(const float4*)(prev + base + G) : make_float4(0, 0, 0, 0);
    float  pL = (j0 > 0)     ? prev[base - 1] : 0.0f;
    float  pR = (j0 < G - 4) ? prev[base + 4] : 0.0f;

    float wc[6] = { expf(m * pL), expf(m * pC.x), expf(m * pC.y),
                    expf(m * pC.z), expf(m * pC.w), expf(m * pR) };
    float wn[4] = { expf(m * pN.x), expf(m * pN.y), expf(m * pN.z), expf(m * pN.w) };
    float ws[4] = { expf(m * pS.x), expf(m * pS.y), expf(m * pS.z), expf(m * pS.w) };

    *(float4*)(g_w + base) = make_float4(wc[1], wc[2], wc[3], wc[4]);

    float4 fC = *(const float4*)(f + base);
    float ff[4] = { fC.x, fC.y, fC.z, fC.w };

    float h[4], Fo[4];
    bool rowIn = (i >= 1 && i <= G - 2);
    const float HH = (1.0f / 1023.0f) * (1.0f / 1023.0f);
#pragma unroll
    for (int k = 0; k < 4; ++k) {
        int j = j0 + k;
        bool in = rowIn && (j >= 1 && j <= G - 2);
        float y3  = 0.5f * (wn[k] + ws[k] + wc[k] + wc[k + 2]) + 2.0f * wc[k + 1];
        float iy3 = 1.0f / y3;
        h[k]  = in ? 0.5f * iy3       : 0.0f;
        Fo[k] = in ? ff[k] * HH * iy3 : 0.0f;
    }
    *(float4*)(g_h + base) = make_float4(h[0], h[1], h[2], h[3]);
    *(float4*)(g_F + base) = make_float4(Fo[0], Fo[1], Fo[2], Fo[3]);
}

// ---------- init u0 (interior = pre, border = 0), zero u1 border ----------
__global__ void k_init(const float* __restrict__ pre) {
    int j = blockIdx.x * blockDim.x + threadIdx.x;
    int i = blockIdx.y;
    int b = blockIdx.z;
    if (j >= G) return;
    int idx = (b * G + i) * G + j;
    bool border = (i == 0 || i == G - 1 || j == 0 || j == G - 1);
    g_u0[idx] = border ? 0.0f : pre[(b * GI + (i - 1)) * GI + (j - 1)];
    if (border) g_u1[idx] = 0.0f;
}

// ---------- one Jacobi sweep: R2 shape (1 row x 4 cols / thread, 256-thr blocks) ----------
template <bool FINAL>
__global__ void __launch_bounds__(256)
k_step(const float* __restrict__ u, float* __restrict__ dst) {
    int j0 = (blockIdx.x * blockDim.x + threadIdx.x) * 4;   // 0..1020
    int i  = blockIdx.y * blockDim.y + threadIdx.y + 1;     // 1..1022
    int b  = blockIdx.z;
    if (i > G - 2) return;
    int idx = (b * G + i) * G + j0;

    float4 uC4 = *(const float4*)(u + idx);
    float4 uN4 = *(const float4*)(u + idx - G);
    float4 uS4 = *(const float4*)(u + idx + G);
    float  uLl = u[idx - 1];
    float  uRr = u[idx + 4];
    float4 wC4 = *(const float4*)(g_w + idx);
    float4 wN4 = *(const float4*)(g_w + idx - G);
    float4 wS4 = *(const float4*)(g_w + idx + G);
    float  wLl = g_w[idx - 1];
    float  wRr = g_w[idx + 4];
    float4 h4 = *(const float4*)(g_h + idx);
    float4 F4 = *(const float4*)(g_F + idx);

    float uc[6] = { uLl, uC4.x, uC4.y, uC4.z, uC4.w, uRr };
    float wc[6] = { wLl, wC4.x, wC4.y, wC4.z, wC4.w, wRr };
    float un[4] = { uN4.x, uN4.y, uN4.z, uN4.w };
    float us[4] = { uS4.x, uS4.y, uS4.z, uS4.w };
    float wn[4] = { wN4.x, wN4.y, wN4.z, wN4.w };
    float ws[4] = { wS4.x, wS4.y, wS4.z, wS4.w };
    float hh[4] = { h4.x, h4.y, h4.z, h4.w };
    float ff[4] = { F4.x, F4.y, F4.z, F4.w };

    float r[4];
#pragma unroll
    for (int k = 0; k < 4; ++k) {
        float uW = uc[k], uE = uc[k + 2];
        float s = wc[k + 1] * (uW + uE + un[k] + us[k]);
        s = fmaf(wc[k],     uW,    s);
        s = fmaf(wc[k + 2], uE,    s);
        s = fmaf(wn[k],     un[k], s);
        s = fmaf(ws[k],     us[k], s);
        r[k] = fmaf(hh[k], s, ff[k]);   // boundary cells: h=F=0 -> exactly 0
    }

    if (FINAL) {
        long obase = ((long)b * GI + (i - 1)) * GI;
#pragma unroll
        for (int k = 0; k < 4; ++k) {
            int j = j0 + k;
            if (j >= 1 && j <= G - 2)
                out_store: dst[obase + (j - 1)] = r[k];
        }
    } else {
        // branchless: edge lanes write correct zeros at j=0 / j=1023
        *(float4*)(dst + idx) = make_float4(r[0], r[1], r[2], r[3]);
    }
}

extern "C" void kernel_launch(void* const* d_in, const int* in_sizes, int n_in,
                              void* d_out, int out_size) {
    const float* pre  = (const float*)d_in[0];   // [B,1,1022,1022]
    const float* f    = (const float*)d_in[1];   // [B,1,1024,1024]
    const float* mu   = (const float*)d_in[2];   // [1]
    const float* prev = (const float*)d_in[3];   // [B,1,1024,1024]
    // d_in[4] = maxiter (fixed = 20 -> 21 total steps)
    float* out = (float*)d_out;

    // resolve device-global addresses once per launch call (host API, capture-safe)
    float *u0p, *u1p;
    cudaGetSymbolAddress((void**)&u0p, g_u0);
    cudaGetSymbolAddress((void**)&u1p, g_u1);

    // precompute
    dim3 pblk(64, 1, 1);                  // 64 thr x 4 cols = 256 cols
    dim3 pgrd(G / 256, G, B);
    k_pre<<<pgrd, pblk>>>(prev, f, mu);

    dim3 iblk(256, 1, 1);
    dim3 igrd((G + 255) / 256, G, B);
    k_init<<<igrd, iblk>>>(pre);

    // 21 Jacobi sweeps, ping-pong; last writes d_out. Exact R2 launch shape.
    dim3 sblk(32, 8, 1);
    dim3 sgrd(G / 128, (GI + 7) / 8, B);  // (8, 128, 4) = 4096 blocks
    for (int t = 0; t < 20; ++t) {
        const float* src = (t & 1) ? u1p : u0p;
        float*       dst = (t & 1) ? u0p : u1p;
        k_step<false><<<sgrd, sblk>>>(src, dst);
    }
    k_step<true><<<sgrd, sblk>>>(u0p, out);   // t=20 even: src u0
}

// round 8
// speedup vs baseline: 1.4583x; 1.0586x over previous
#include <cuda_runtime.h>
#include <math.h>

#define G      1024
#define GI     (G - 2)
#define B      4
#define N_TOT  (B * G * G)

__device__ float g_w  [N_TOT];   // exp(mu * prev_pre)
__device__ float g_h  [N_TOT];   // 0.5 / y3   (0 on boundary)
__device__ float g_F  [N_TOT];   // f*H^2 / y3 (0 on boundary)
__device__ float g_u0 [N_TOT];
__device__ float g_u1 [N_TOT];

// ---------- fused precompute + init: w, h, F, u0 (u1 border) in one pass ----------
// blockDim (64,4): block tile 256 cols x 4 rows -> prev halo rows L1-shared (1.5x L2).
__global__ void __launch_bounds__(256)
k_pre(const float* __restrict__ prev, const float* __restrict__ f,
      const float* __restrict__ mu, const float* __restrict__ pre) {
    int j0 = (blockIdx.x * blockDim.x + threadIdx.x) * 4;   // 0..1020
    int i  = blockIdx.y * blockDim.y + threadIdx.y;         // 0..1023
    int b  = blockIdx.z;
    int base = (b * G + i) * G + j0;
    float m = mu[0];

    float4 pC = *(const float4*)(prev + base);
    float4 pN = (i > 0)     ? *(const float4*)(prev + base - G) : make_float4(0, 0, 0, 0);
    float4 pS = (i < G - 1) ? *(const float4*)(prev + base + G) : make_float4(0, 0, 0, 0);
    float  pL = (j0 > 0)     ? prev[base - 1] : 0.0f;
    float  pR = (j0 < G - 4) ? prev[base + 4] : 0.0f;

    float wc[6] = { expf(m * pL), expf(m * pC.x), expf(m * pC.y),
                    expf(m * pC.z), expf(m * pC.w), expf(m * pR) };
    float wn[4] = { expf(m * pN.x), expf(m * pN.y), expf(m * pN.z), expf(m * pN.w) };
    float ws[4] = { expf(m * pS.x), expf(m * pS.y), expf(m * pS.z), expf(m * pS.w) };

    *(float4*)(g_w + base) = make_float4(wc[1], wc[2], wc[3], wc[4]);

    float4 fC = *(const float4*)(f + base);
    float ff[4] = { fC.x, fC.y, fC.z, fC.w };

    bool rowIn = (i >= 1 && i <= G - 2);
    const float HH = (1.0f / 1023.0f) * (1.0f / 1023.0f);
    float h[4], Fo[4], u0v[4];
#pragma unroll
    for (int k = 0; k < 4; ++k) {
        int j = j0 + k;
        bool in = rowIn && (j >= 1 && j <= G - 2);
        float y3  = 0.5f * (wn[k] + ws[k] + wc[k] + wc[k + 2]) + 2.0f * wc[k + 1];
        float iy3 = 1.0f / y3;
        h[k]  = in ? 0.5f * iy3       : 0.0f;
        Fo[k] = in ? ff[k] * HH * iy3 : 0.0f;
        // init u0: interior = pre (unpadded 1022x1022), border = 0
        u0v[k] = in ? pre[((long)b * GI + (i - 1)) * GI + (j - 1)] : 0.0f;
    }
    *(float4*)(g_h  + base) = make_float4(h[0], h[1], h[2], h[3]);
    *(float4*)(g_F  + base) = make_float4(Fo[0], Fo[1], Fo[2], Fo[3]);
    *(float4*)(g_u0 + base) = make_float4(u0v[0], u0v[1], u0v[2], u0v[3]);

    // u1: only border must be zeroed (interior overwritten by sweep 1)
    if (i == 0 || i == G - 1) {
        *(float4*)(g_u1 + base) = make_float4(0, 0, 0, 0);
    } else if (j0 == 0) {
        g_u1[base] = 0.0f;
    } else if (j0 == G - 4) {
        g_u1[base + 3] = 0.0f;
    }
}

// ---------- one Jacobi sweep: R2/R7 shape (1 row x 4 cols / thread, 256-thr blocks) ----------
template <bool FINAL>
__global__ void __launch_bounds__(256)
k_step(const float* __restrict__ u, float* __restrict__ dst) {
    int j0 = (blockIdx.x * blockDim.x + threadIdx.x) * 4;   // 0..1020
    int i  = blockIdx.y * blockDim.y + threadIdx.y + 1;     // 1..1022
    int b  = blockIdx.z;
    if (i > G - 2) return;
    int idx = (b * G + i) * G + j0;

    float4 uC4 = *(const float4*)(u + idx);
    float4 uN4 = *(const float4*)(u + idx - G);
    float4 uS4 = *(const float4*)(u + idx + G);
    float  uLl = u[idx - 1];
    float  uRr = u[idx + 4];
    float4 wC4 = *(const float4*)(g_w + idx);
    float4 wN4 = *(const float4*)(g_w + idx - G);
    float4 wS4 = *(const float4*)(g_w + idx + G);
    float  wLl = g_w[idx - 1];
    float  wRr = g_w[idx + 4];
    float4 h4 = *(const float4*)(g_h + idx);
    float4 F4 = *(const float4*)(g_F + idx);

    float uc[6] = { uLl, uC4.x, uC4.y, uC4.z, uC4.w, uRr };
    float wc[6] = { wLl, wC4.x, wC4.y, wC4.z, wC4.w, wRr };
    float un[4] = { uN4.x, uN4.y, uN4.z, uN4.w };
    float us[4] = { uS4.x, uS4.y, uS4.z, uS4.w };
    float wn[4] = { wN4.x, wN4.y, wN4.z, wN4.w };
    float ws[4] = { wS4.x, wS4.y, wS4.z, wS4.w };
    float hh[4] = { h4.x, h4.y, h4.z, h4.w };
    float ff[4] = { F4.x, F4.y, F4.z, F4.w };

    float r[4];
#pragma unroll
    for (int k = 0; k < 4; ++k) {
        float uW = uc[k], uE = uc[k + 2];
        float s = wc[k + 1] * (uW + uE + un[k] + us[k]);
        s = fmaf(wc[k],     uW,    s);
        s = fmaf(wc[k + 2], uE,    s);
        s = fmaf(wn[k],     un[k], s);
        s = fmaf(ws[k],     us[k], s);
        r[k] = fmaf(hh[k], s, ff[k]);   // boundary cells: h=F=0 -> exactly 0
    }

    if (FINAL) {
        long obase = ((long)b * GI + (i - 1)) * GI;
#pragma unroll
        for (int k = 0; k < 4; ++k) {
            int j = j0 + k;
            if (j >= 1 && j <= G - 2)
                dst[obase + (j - 1)] = r[k];
        }
    } else {
        // branchless: edge lanes write correct zeros at j=0 / j=1023
        *(float4*)(dst + idx) = make_float4(r[0], r[1], r[2], r[3]);
    }
}

extern "C" void kernel_launch(void* const* d_in, const int* in_sizes, int n_in,
                              void* d_out, int out_size) {
    const float* pre  = (const float*)d_in[0];   // [B,1,1022,1022]
    const float* f    = (const float*)d_in[1];   // [B,1,1024,1024]
    const float* mu   = (const float*)d_in[2];   // [1]
    const float* prev = (const float*)d_in[3];   // [B,1,1024,1024]
    // d_in[4] = maxiter (fixed = 20 -> 21 total steps)
    float* out = (float*)d_out;

    float *u0p, *u1p;
    cudaGetSymbolAddress((void**)&u0p, g_u0);
    cudaGetSymbolAddress((void**)&u1p, g_u1);

    // fused precompute + init: blockDim (64,4), tile 256x4
    dim3 pblk(64, 4, 1);
    dim3 pgrd(G / 256, G / 4, B);     // (4, 256, 4)
    k_pre<<<pgrd, pblk>>>(prev, f, mu, pre);

    // 21 Jacobi sweeps, ping-pong; last writes d_out.
    dim3 sblk(32, 8, 1);
    dim3 sgrd(G / 128, (GI + 7) / 8, B);  // (8, 128, 4) = 4096 blocks
    for (int t = 0; t < 20; ++t) {
        const float* src = (t & 1) ? u1p : u0p;
        float*       dst = (t & 1) ? u0p : u1p;
        k_step<false><<<sgrd, sblk>>>(src, dst);
    }
    k_step<true><<<sgrd, sblk>>>(u0p, out);   // t=20 even: src u0
}

// round 9
// speedup vs baseline: 1.4662x; 1.0054x over previous
#include <cuda_runtime.h>
#include <math.h>

#define G      1024
#define GI     (G - 2)
#define B      4
#define N_TOT  (B * G * G)

__device__ float g_w  [N_TOT];   // exp(mu * prev_pre)
__device__ float g_h  [N_TOT];   // 0.5 / y3   (0 on boundary)
__device__ float g_F  [N_TOT];   // f*H^2 / y3 (0 on boundary)
__device__ float g_u0 [N_TOT];
__device__ float g_u1 [N_TOT];

__device__ __forceinline__ float4 ldcs4(const float* p) {
    return __ldcs((const float4*)p);
}

// ---------- fused precompute + init: w, h, F, u0 (u1 border) in one pass ----------
// blockDim (32,8): tile 128 cols x 8 rows -> prev halo 1.25x. One-shot inputs via __ldcs.
__global__ void __launch_bounds__(256)
k_pre(const float* __restrict__ prev, const float* __restrict__ f,
      const float* __restrict__ mu, const float* __restrict__ pre) {
    int j0 = (blockIdx.x * blockDim.x + threadIdx.x) * 4;   // 0..1020
    int i  = blockIdx.y * blockDim.y + threadIdx.y;         // 0..1023
    int b  = blockIdx.z;
    int base = (b * G + i) * G + j0;
    float m = mu[0];

    float4 pC = ldcs4(prev + base);
    float4 pN = (i > 0)     ? ldcs4(prev + base - G) : make_float4(0, 0, 0, 0);
    float4 pS = (i < G - 1) ? ldcs4(prev + base + G) : make_float4(0, 0, 0, 0);
    float  pL = (j0 > 0)     ? __ldcs(prev + base - 1) : 0.0f;
    float  pR = (j0 < G - 4) ? __ldcs(prev + base + 4) : 0.0f;

    float wc[6] = { expf(m * pL), expf(m * pC.x), expf(m * pC.y),
                    expf(m * pC.z), expf(m * pC.w), expf(m * pR) };
    float wn[4] = { expf(m * pN.x), expf(m * pN.y), expf(m * pN.z), expf(m * pN.w) };
    float ws[4] = { expf(m * pS.x), expf(m * pS.y), expf(m * pS.z), expf(m * pS.w) };

    *(float4*)(g_w + base) = make_float4(wc[1], wc[2], wc[3], wc[4]);

    float4 fC = ldcs4(f + base);
    float ff[4] = { fC.x, fC.y, fC.z, fC.w };

    bool rowIn = (i >= 1 && i <= G - 2);
    const float HH = (1.0f / 1023.0f) * (1.0f / 1023.0f);
    float h[4], Fo[4], u0v[4];
#pragma unroll
    for (int k = 0; k < 4; ++k) {
        int j = j0 + k;
        bool in = rowIn && (j >= 1 && j <= G - 2);
        float y3  = 0.5f * (wn[k] + ws[k] + wc[k] + wc[k + 2]) + 2.0f * wc[k + 1];
        float iy3 = 1.0f / y3;
        h[k]  = in ? 0.5f * iy3       : 0.0f;
        Fo[k] = in ? ff[k] * HH * iy3 : 0.0f;
        u0v[k] = in ? __ldcs(pre + ((long)b * GI + (i - 1)) * GI + (j - 1)) : 0.0f;
    }
    *(float4*)(g_h  + base) = make_float4(h[0], h[1], h[2], h[3]);
    *(float4*)(g_F  + base) = make_float4(Fo[0], Fo[1], Fo[2], Fo[3]);
    *(float4*)(g_u0 + base) = make_float4(u0v[0], u0v[1], u0v[2], u0v[3]);

    // u1: only border must be zeroed (interior overwritten by sweep 1)
    if (i == 0 || i == G - 1) {
        *(float4*)(g_u1 + base) = make_float4(0, 0, 0, 0);
    } else if (j0 == 0) {
        g_u1[base] = 0.0f;
    } else if (j0 == G - 4) {
        g_u1[base + 3] = 0.0f;
    }
}

// ---------- one Jacobi sweep: proven shape (1 row x 4 cols / thread, (32,8) blocks) ----------
template <bool FINAL>
__global__ void __launch_bounds__(256)
k_step(const float* __restrict__ u, float* __restrict__ dst) {
    int j0 = (blockIdx.x * blockDim.x + threadIdx.x) * 4;   // 0..1020
    int i  = blockIdx.y * blockDim.y + threadIdx.y + 1;     // 1..1022
    int b  = blockIdx.z;
    if (i > G - 2) return;
    int idx = (b * G + i) * G + j0;

    float4 uC4 = *(const float4*)(u + idx);
    float4 uN4 = *(const float4*)(u + idx - G);
    float4 uS4 = *(const float4*)(u + idx + G);
    float  uLl = u[idx - 1];
    float  uRr = u[idx + 4];
    float4 wC4 = *(const float4*)(g_w + idx);
    float4 wN4 = *(const float4*)(g_w + idx - G);
    float4 wS4 = *(const float4*)(g_w + idx + G);
    float  wLl = g_w[idx - 1];
    float  wRr = g_w[idx + 4];
    float4 h4 = *(const float4*)(g_h + idx);
    float4 F4 = *(const float4*)(g_F + idx);

    float uc[6] = { uLl, uC4.x, uC4.y, uC4.z, uC4.w, uRr };
    float wc[6] = { wLl, wC4.x, wC4.y, wC4.z, wC4.w, wRr };
    float un[4] = { uN4.x, uN4.y, uN4.z, uN4.w };
    float us[4] = { uS4.x, uS4.y, uS4.z, uS4.w };
    float wn[4] = { wN4.x, wN4.y, wN4.z, wN4.w };
    float ws[4] = { wS4.x, wS4.y, wS4.z, wS4.w };
    float hh[4] = { h4.x, h4.y, h4.z, h4.w };
    float ff[4] = { F4.x, F4.y, F4.z, F4.w };

    float r[4];
#pragma unroll
    for (int k = 0; k < 4; ++k) {
        float uW = uc[k], uE = uc[k + 2];
        float s = wc[k + 1] * (uW + uE + un[k] + us[k]);
        s = fmaf(wc[k],     uW,    s);
        s = fmaf(wc[k + 2], uE,    s);
        s = fmaf(wn[k],     un[k], s);
        s = fmaf(ws[k],     us[k], s);
        r[k] = fmaf(hh[k], s, ff[k]);   // boundary cells: h=F=0 -> exactly 0
    }

    if (FINAL) {
        long obase = ((long)b * GI + (i - 1)) * GI;
#pragma unroll
        for (int k = 0; k < 4; ++k) {
            int j = j0 + k;
            if (j >= 1 && j <= G - 2)
                __stcs(dst + obase + (j - 1), r[k]);   // streaming: never re-read
        }
    } else {
        *(float4*)(dst + idx) = make_float4(r[0], r[1], r[2], r[3]);
    }
}

extern "C" void kernel_launch(void* const* d_in, const int* in_sizes, int n_in,
                              void* d_out, int out_size) {
    const float* pre  = (const float*)d_in[0];   // [B,1,1022,1022]
    const float* f    = (const float*)d_in[1];   // [B,1,1024,1024]
    const float* mu   = (const float*)d_in[2];   // [1]
    const float* prev = (const float*)d_in[3];   // [B,1,1024,1024]
    // d_in[4] = maxiter (fixed = 20 -> 21 total steps)
    float* out = (float*)d_out;

    float *u0p, *u1p;
    cudaGetSymbolAddress((void**)&u0p, g_u0);
    cudaGetSymbolAddress((void**)&u1p, g_u1);

    // fused precompute + init: blockDim (32,8), tile 128x8
    dim3 pblk(32, 8, 1);
    dim3 pgrd(G / 128, G / 8, B);        // (8, 128, 4)
    k_pre<<<pgrd, pblk>>>(prev, f, mu, pre);

    // 21 Jacobi sweeps, ping-pong; last writes d_out.
    dim3 sblk(32, 8, 1);
    dim3 sgrd(G / 128, (GI + 7) / 8, B);  // (8, 128, 4) = 4096 blocks
    for (int t = 0; t < 20; ++t) {
        const float* src = (t & 1) ? u1p : u0p;
        float*       dst = (t & 1) ? u0p : u1p;
        k_step<false><<<sgrd, sblk>>>(src, dst);
    }
    k_step<true><<<sgrd, sblk>>>(u0p, out);   // t=20 even: src u0
}

// round 10
// speedup vs baseline: 1.7718x; 1.2085x over previous
#include <cuda_runtime.h>
#include <math.h>

#define G      1024
#define GI     (G - 2)
#define B      4
#define N_TOT  (B * G * G)

__device__ float g_w  [N_TOT];   // exp(mu * prev_pre)
__device__ float g_h  [N_TOT];   // 0.5 / y3   (0 on boundary)
__device__ float g_F  [N_TOT];   // f*H^2 / y3 (0 on boundary)
__device__ float g_u0 [N_TOT];
__device__ float g_u1 [N_TOT];

__device__ __forceinline__ float4 ldcs4(const float* p) {
    return __ldcs((const float4*)p);
}

// ---------- fused precompute + init: w, h, F, u0 (u1 border) in one pass ----------
__global__ void __launch_bounds__(256)
k_pre(const float* __restrict__ prev, const float* __restrict__ f,
      const float* __restrict__ mu, const float* __restrict__ pre) {
    int j0 = (blockIdx.x * blockDim.x + threadIdx.x) * 4;   // 0..1020
    int i  = blockIdx.y * blockDim.y + threadIdx.y;         // 0..1023
    int b  = blockIdx.z;
    int base = (b * G + i) * G + j0;
    float m = mu[0];

    float4 pC = ldcs4(prev + base);
    float4 pN = (i > 0)     ? ldcs4(prev + base - G) : make_float4(0, 0, 0, 0);
    float4 pS = (i < G - 1) ? ldcs4(prev + base + G) : make_float4(0, 0, 0, 0);
    float  pL = (j0 > 0)     ? __ldcs(prev + base - 1) : 0.0f;
    float  pR = (j0 < G - 4) ? __ldcs(prev + base + 4) : 0.0f;

    float wc[6] = { expf(m * pL), expf(m * pC.x), expf(m * pC.y),
                    expf(m * pC.z), expf(m * pC.w), expf(m * pR) };
    float wn[4] = { expf(m * pN.x), expf(m * pN.y), expf(m * pN.z), expf(m * pN.w) };
    float ws[4] = { expf(m * pS.x), expf(m * pS.y), expf(m * pS.z), expf(m * pS.w) };

    *(float4*)(g_w + base) = make_float4(wc[1], wc[2], wc[3], wc[4]);

    float4 fC = ldcs4(f + base);
    float ff[4] = { fC.x, fC.y, fC.z, fC.w };

    bool rowIn = (i >= 1 && i <= G - 2);
    const float HH = (1.0f / 1023.0f) * (1.0f / 1023.0f);
    float h[4], Fo[4], u0v[4];
#pragma unroll
    for (int k = 0; k < 4; ++k) {
        int j = j0 + k;
        bool in = rowIn && (j >= 1 && j <= G - 2);
        float y3  = 0.5f * (wn[k] + ws[k] + wc[k] + wc[k + 2]) + 2.0f * wc[k + 1];
        float iy3 = 1.0f / y3;
        h[k]  = in ? 0.5f * iy3       : 0.0f;
        Fo[k] = in ? ff[k] * HH * iy3 : 0.0f;
        u0v[k] = in ? __ldcs(pre + ((long)b * GI + (i - 1)) * GI + (j - 1)) : 0.0f;
    }
    *(float4*)(g_h  + base) = make_float4(h[0], h[1], h[2], h[3]);
    *(float4*)(g_F  + base) = make_float4(Fo[0], Fo[1], Fo[2], Fo[3]);
    *(float4*)(g_u0 + base) = make_float4(u0v[0], u0v[1], u0v[2], u0v[3]);

    if (i == 0 || i == G - 1) {
        *(float4*)(g_u1 + base) = make_float4(0, 0, 0, 0);
    } else if (j0 == 0) {
        g_u1[base] = 0.0f;
    } else if (j0 == G - 4) {
        g_u1[base + 3] = 0.0f;
    }
}

// ---------- one Jacobi sweep with PDL phases ----------
// PDL=true: invariant w/h/F loads issue BEFORE griddepcontrol.wait (nobody writes
// them after k_pre); u loads after wait; launch_dependents fires right after the
// u loads so the next sweep's invariant phase overlaps our compute/store tail.
template <bool FINAL, bool PDL>
__global__ void __launch_bounds__(256)
k_step(const float* __restrict__ u, float* __restrict__ dst) {
    int j0 = (blockIdx.x * blockDim.x + threadIdx.x) * 4;   // 0..1020
    int i  = blockIdx.y * blockDim.y + threadIdx.y + 1;     // 1..1024
    int b  = blockIdx.z;
    if (i > G - 2) {
        if (PDL) asm volatile("griddepcontrol.launch_dependents;" ::: "memory");
        return;
    }
    int idx = (b * G + i) * G + j0;

    // --- phase A: iteration-invariant operands (safe pre-dependency) ---
    float4 wC4 = *(const float4*)(g_w + idx);
    float4 wN4 = *(const float4*)(g_w + idx - G);
    float4 wS4 = *(const float4*)(g_w + idx + G);
    float  wLl = g_w[idx - 1];
    float  wRr = g_w[idx + 4];
    float4 h4 = *(const float4*)(g_h + idx);
    float4 F4 = *(const float4*)(g_F + idx);

    if (PDL) asm volatile("griddepcontrol.wait;" ::: "memory");

    // --- phase B: dependent u loads ---
    float4 uC4 = *(const float4*)(u + idx);
    float4 uN4 = *(const float4*)(u + idx - G);
    float4 uS4 = *(const float4*)(u + idx + G);
    float  uLl = u[idx - 1];
    float  uRr = u[idx + 4];

    if (PDL) asm volatile("griddepcontrol.launch_dependents;" ::: "memory");

    float uc[6] = { uLl, uC4.x, uC4.y, uC4.z, uC4.w, uRr };
    float wc[6] = { wLl, wC4.x, wC4.y, wC4.z, wC4.w, wRr };
    float un[4] = { uN4.x, uN4.y, uN4.z, uN4.w };
    float us[4] = { uS4.x, uS4.y, uS4.z, uS4.w };
    float wn[4] = { wN4.x, wN4.y, wN4.z, wN4.w };
    float ws[4] = { wS4.x, wS4.y, wS4.z, wS4.w };
    float hh[4] = { h4.x, h4.y, h4.z, h4.w };
    float ff[4] = { F4.x, F4.y, F4.z, F4.w };

    float r[4];
#pragma unroll
    for (int k = 0; k < 4; ++k) {
        float uW = uc[k], uE = uc[k + 2];
        float s = wc[k + 1] * (uW + uE + un[k] + us[k]);
        s = fmaf(wc[k],     uW,    s);
        s = fmaf(wc[k + 2], uE,    s);
        s = fmaf(wn[k],     un[k], s);
        s = fmaf(ws[k],     us[k], s);
        r[k] = fmaf(hh[k], s, ff[k]);   // boundary cells: h=F=0 -> exactly 0
    }

    if (FINAL) {
        long obase = ((long)b * GI + (i - 1)) * GI;
#pragma unroll
        for (int k = 0; k < 4; ++k) {
            int j = j0 + k;
            if (j >= 1 && j <= G - 2)
                __stcs(dst + obase + (j - 1), r[k]);
        }
    } else {
        *(float4*)(dst + idx) = make_float4(r[0], r[1], r[2], r[3]);
    }
}

extern "C" void kernel_launch(void* const* d_in, const int* in_sizes, int n_in,
                              void* d_out, int out_size) {
    const float* pre  = (const float*)d_in[0];   // [B,1,1022,1022]
    const float* f    = (const float*)d_in[1];   // [B,1,1024,1024]
    const float* mu   = (const float*)d_in[2];   // [1]
    const float* prev = (const float*)d_in[3];   // [B,1,1024,1024]
    // d_in[4] = maxiter (fixed = 20 -> 21 total steps)
    float* out = (float*)d_out;

    float *u0p, *u1p;
    cudaGetSymbolAddress((void**)&u0p, g_u0);
    cudaGetSymbolAddress((void**)&u1p, g_u1);

    // fused precompute + init
    dim3 pblk(32, 8, 1);
    dim3 pgrd(G / 128, G / 8, B);
    k_pre<<<pgrd, pblk>>>(prev, f, mu, pre);

    dim3 sblk(32, 8, 1);
    dim3 sgrd(G / 128, (GI + 7) / 8, B);  // 4096 blocks

    // sweep 1: normal launch (its invariant pre-loads depend on k_pre's writes)
    k_step<false, false><<<sgrd, sblk>>>(u0p, u1p);

    // sweeps 2..21: PDL launches
    cudaLaunchConfig_t cfg = {};
    cfg.gridDim = sgrd;
    cfg.blockDim = sblk;
    cfg.dynamicSmemBytes = 0;
    cfg.stream = 0;
    cudaLaunchAttribute at;
    at.id = cudaLaunchAttributeProgrammaticStreamSerialization;
    at.val.programmaticStreamSerializationAllowed = 1;
    cfg.attrs = &at;
    cfg.numAttrs = 1;

    for (int t = 1; t < 20; ++t) {
        const float* src = (t & 1) ? u1p : u0p;
        float*       dst = (t & 1) ? u0p : u1p;
        cudaLaunchKernelEx(&cfg, k_step<false, true>, src, dst);
    }
    cudaLaunchKernelEx(&cfg, k_step<true, true>, (const float*)u0p, out);  // t=20: src u0
}